// round 1
// baseline (speedup 1.0000x reference)
#include <cuda_runtime.h>
#include <cuda_bf16.h>

typedef unsigned long long ULL;

__device__ __forceinline__ ULL f2pack(float x, float y) {
    ULL r; asm("mov.b64 %0, {%1,%2};" : "=l"(r) : "f"(x), "f"(y)); return r;
}
__device__ __forceinline__ float2 f2unpack(ULL v) {
    float2 r; asm("mov.b64 {%0,%1}, %2;" : "=f"(r.x), "=f"(r.y) : "l"(v)); return r;
}
__device__ __forceinline__ ULL ffma2(ULL a, ULL b, ULL c) {
    ULL d; asm("fma.rn.f32x2 %0, %1, %2, %3;" : "=l"(d) : "l"(a), "l"(b), "l"(c)); return d;
}

// smem layout (in ULL units):
//   A2   [16][64]          offset 0      (1024)   X tile, row-pairs packed
//   Wt   [16][272]         offset 1024   (4352)   weight tile, {w,w} dup, idx kk*272 + (col>>4)*17 + (col&15)
//   h2   [64][257]         offset 5376   (16448)  activations, row-pairs packed
//   W3d  [256*24]          offset 21824  (6144)   W3 dup
//   logit_s (float)        reuses A2/Wt region: 128*25 floats = 1600 ULL < 5376
#define SMEM_ULL 27968
#define SMEM_BYTES (SMEM_ULL * 8)

__global__ void __launch_bounds__(256, 1) fused_mlp_topk(
    const float* __restrict__ X,
    const float* __restrict__ W1, const float* __restrict__ b1,
    const float* __restrict__ W2, const float* __restrict__ b2,
    const float* __restrict__ W3, const float* __restrict__ b3,
    float* __restrict__ out, int B)
{
    extern __shared__ ULL sm[];
    ULL* A2  = sm;
    ULL* Wt  = sm + 1024;
    ULL* h2  = sm + 5376;
    ULL* W3d = sm + 21824;
    float* logit_s = (float*)sm;

    const int tid = threadIdx.x;
    const int tx  = tid & 15;
    const int ty  = tid >> 4;
    const int bm0 = blockIdx.x * 128;

    // Load W3 duplicated into smem once (256*24 entries)
    #pragma unroll
    for (int t = 0; t < 24; ++t) {
        int e = tid + t * 256;
        float w = W3[e];
        W3d[e] = f2pack(w, w);
    }

    ULL acc[4][16];

    // ================= Layer 1: h1 = relu(X @ W1 + b1) =================
    #pragma unroll
    for (int p = 0; p < 4; ++p)
        #pragma unroll
        for (int j = 0; j < 16; ++j) acc[p][j] = 0ULL;

    for (int kc = 0; kc < 16; ++kc) {
        const int k0 = kc * 16;
        // stage X tile (128 rows x 16 k) as row-pairs: A2[kk][rp]
        #pragma unroll
        for (int t = 0; t < 4; ++t) {
            int e  = tid + t * 256;
            int kk = e >> 6, rp = e & 63;
            const float* xp = X + (size_t)(bm0 + 2 * rp) * 256 + (k0 + kk);
            A2[kk * 64 + rp] = f2pack(xp[0], xp[256]);
        }
        // stage W1 tile (16 k x 256 n), duplicated, interleaved layout
        #pragma unroll
        for (int t = 0; t < 16; ++t) {
            int e   = tid + t * 256;
            int kk  = e >> 8, col = e & 255;
            float w = W1[(k0 + kk) * 256 + col];
            Wt[kk * 272 + (col >> 4) * 17 + (col & 15)] = f2pack(w, w);
        }
        __syncthreads();
        #pragma unroll
        for (int kk = 0; kk < 16; ++kk) {
            ULL a[4], bf[16];
            #pragma unroll
            for (int p = 0; p < 4; ++p) a[p] = A2[kk * 64 + ty * 4 + p];
            #pragma unroll
            for (int j = 0; j < 16; ++j) bf[j] = Wt[kk * 272 + j * 17 + tx];
            #pragma unroll
            for (int p = 0; p < 4; ++p)
                #pragma unroll
                for (int j = 0; j < 16; ++j)
                    acc[p][j] = ffma2(a[p], bf[j], acc[p][j]);
        }
        __syncthreads();
    }
    // epilogue 1: bias + relu -> h2
    #pragma unroll
    for (int j = 0; j < 16; ++j) {
        float bb = b1[j * 16 + tx];
        #pragma unroll
        for (int p = 0; p < 4; ++p) {
            float2 v = f2unpack(acc[p][j]);
            v.x = fmaxf(v.x + bb, 0.0f);
            v.y = fmaxf(v.y + bb, 0.0f);
            h2[(ty * 4 + p) * 257 + (j * 16 + tx)] = f2pack(v.x, v.y);
        }
    }
    __syncthreads();

    // ================= Layer 2: h2 = relu(h1 @ W2 + b2) =================
    #pragma unroll
    for (int p = 0; p < 4; ++p)
        #pragma unroll
        for (int j = 0; j < 16; ++j) acc[p][j] = 0ULL;

    for (int kc = 0; kc < 16; ++kc) {
        const int k0 = kc * 16;
        #pragma unroll
        for (int t = 0; t < 16; ++t) {
            int e   = tid + t * 256;
            int kk  = e >> 8, col = e & 255;
            float w = W2[(k0 + kk) * 256 + col];
            Wt[kk * 272 + (col >> 4) * 17 + (col & 15)] = f2pack(w, w);
        }
        __syncthreads();
        #pragma unroll
        for (int kk = 0; kk < 16; ++kk) {
            ULL a[4], bf[16];
            #pragma unroll
            for (int p = 0; p < 4; ++p) a[p] = h2[(ty * 4 + p) * 257 + (k0 + kk)];
            #pragma unroll
            for (int j = 0; j < 16; ++j) bf[j] = Wt[kk * 272 + j * 17 + tx];
            #pragma unroll
            for (int p = 0; p < 4; ++p)
                #pragma unroll
                for (int j = 0; j < 16; ++j)
                    acc[p][j] = ffma2(a[p], bf[j], acc[p][j]);
        }
        __syncthreads();
    }
    // epilogue 2: bias + relu -> h2 (overwrite; all reads done past the sync)
    #pragma unroll
    for (int j = 0; j < 16; ++j) {
        float bb = b2[j * 16 + tx];
        #pragma unroll
        for (int p = 0; p < 4; ++p) {
            float2 v = f2unpack(acc[p][j]);
            v.x = fmaxf(v.x + bb, 0.0f);
            v.y = fmaxf(v.y + bb, 0.0f);
            h2[(ty * 4 + p) * 257 + (j * 16 + tx)] = f2pack(v.x, v.y);
        }
    }
    __syncthreads();

    // ================= Layer 3: logits = h2 @ W3 + b3 =================
    {
        const int rp3 = tid >> 2;   // row pair 0..63
        const int q   = tid & 3;    // col group 0..3 (6 cols each)
        ULL a3[6];
        #pragma unroll
        for (int j = 0; j < 6; ++j) a3[j] = 0ULL;
        #pragma unroll 8
        for (int k = 0; k < 256; ++k) {
            ULL av = h2[rp3 * 257 + k];
            #pragma unroll
            for (int j = 0; j < 6; ++j)
                a3[j] = ffma2(av, W3d[k * 24 + q * 6 + j], a3[j]);
        }
        #pragma unroll
        for (int j = 0; j < 6; ++j) {
            int c = q * 6 + j;
            float bb = b3[c];
            float2 v = f2unpack(a3[j]);
            logit_s[(2 * rp3) * 25 + c]     = v.x + bb;
            logit_s[(2 * rp3 + 1) * 25 + c] = v.y + bb;
        }
    }
    __syncthreads();

    // ================= Top-6 of 22 selected logits + write =================
    if (tid < 128) {
        const int row = bm0 + tid;
        float v[24];
        #pragma unroll
        for (int c = 0; c < 24; ++c) v[c] = logit_s[tid * 25 + c];

        unsigned chosen = 1u | (1u << 12);   // cols 0 and 12 always 1
        #pragma unroll
        for (int it = 0; it < 6; ++it) {
            float best = -3.402823466e38f;
            int bi = 1;
            #pragma unroll
            for (int c = 1; c < 24; ++c) {
                if (c == 12) continue;
                bool free_ = !((chosen >> c) & 1u);
                if (free_ && v[c] > best) { best = v[c]; bi = c; }  // strict > : lower index wins ties
            }
            chosen |= (1u << bi);
        }

        float o[24];
        #pragma unroll
        for (int c = 0; c < 24; ++c) o[c] = ((chosen >> c) & 1u) ? 1.0f : 0.0f;
        float4* op = (float4*)(out + (size_t)row * 24);
        #pragma unroll
        for (int g = 0; g < 6; ++g)
            op[g] = make_float4(o[4 * g], o[4 * g + 1], o[4 * g + 2], o[4 * g + 3]);
    }
}

extern "C" void kernel_launch(void* const* d_in, const int* in_sizes, int n_in,
                              void* d_out, int out_size) {
    const float* X  = (const float*)d_in[0];
    const float* W1 = (const float*)d_in[1];
    const float* b1 = (const float*)d_in[2];
    const float* W2 = (const float*)d_in[3];
    const float* b2 = (const float*)d_in[4];
    const float* W3 = (const float*)d_in[5];
    const float* b3 = (const float*)d_in[6];
    float* out = (float*)d_out;

    int B = in_sizes[0] / 256;
    cudaFuncSetAttribute(fused_mlp_topk, cudaFuncAttributeMaxDynamicSharedMemorySize, SMEM_BYTES);
    fused_mlp_topk<<<B / 128, 256, SMEM_BYTES>>>(X, W1, b1, W2, b2, W3, b3, out, B);
}

// round 2
// speedup vs baseline: 1.2892x; 1.2892x over previous
#include <cuda_runtime.h>

typedef unsigned long long ULL;

__device__ __forceinline__ ULL f2dup(float x) {
    ULL r; asm("mov.b64 %0, {%1,%1};" : "=l"(r) : "f"(x)); return r;
}
__device__ __forceinline__ float2 f2unpack(ULL v) {
    float2 r; asm("mov.b64 {%0,%1}, %2;" : "=f"(r.x), "=f"(r.y) : "l"(v)); return r;
}
__device__ __forceinline__ ULL ffma2(ULL a, ULL b, ULL c) {
    ULL d; asm("fma.rn.f32x2 %0, %1, %2, %3;" : "=l"(d) : "l"(a), "l"(b), "l"(c)); return d;
}

// smem layout in floats:
//   h    [128][257]   @ 0        (32896)  activations
//   Xs   2x[128][17]  @ 32896    (4352)   X tile double buffer
//   Wt   2x[16][256]  @ 37248    (8192)   W tile double buffer (plain layout)
//   W3s  [256][24]    @ 45440    (6144)
//   logit_s [128][25] overlays Xs/Wt region
#define H_STRIDE 257
#define OFF_XS   32896
#define XS_BUF   2176
#define OFF_WT   37248
#define WT_BUF   4096
#define OFF_W3   45440
#define SMEM_FLOATS 51584
#define SMEM_BYTES (SMEM_FLOATS * 4)

__global__ void __launch_bounds__(256, 1) fused_mlp_topk(
    const float* __restrict__ X,
    const float* __restrict__ W1, const float* __restrict__ b1,
    const float* __restrict__ W2, const float* __restrict__ b2,
    const float* __restrict__ W3, const float* __restrict__ b3,
    float* __restrict__ out)
{
    extern __shared__ float sm[];
    float* h       = sm;
    float* Xs      = sm + OFF_XS;
    float* Wt      = sm + OFF_WT;
    float* W3s     = sm + OFF_W3;
    float* logit_s = sm + OFF_XS;   // overlay, used only after Xs/Wt are dead

    const int tid = threadIdx.x;
    const int tr  = tid & 15;       // row group 0..15  (rows tr + 16p)
    const int tc  = tid >> 4;       // colpair group 0..15 (colpairs tc + 16j)
    const int bm0 = blockIdx.x * 128;

    // stage W3 once (plain contiguous copy)
    #pragma unroll
    for (int u = 0; u < 6; ++u) {
        int i = tid + u * 256;
        ((float4*)W3s)[i] = ((const float4*)W3)[i];
    }

    ULL acc[8][8];

    // ---------------- Layer 1: h = relu(X @ W1 + b1) ----------------
    #pragma unroll
    for (int p = 0; p < 8; ++p)
        #pragma unroll
        for (int j = 0; j < 8; ++j) acc[p][j] = 0ULL;

    // initial stage (kc = 0 -> buffer 0)
    {
        float* Xb = Xs;
        #pragma unroll
        for (int u = 0; u < 2; ++u) {
            int t = tid + u * 256;
            int row = t >> 2, ku = (t & 3) * 4;
            float4 v = *(const float4*)(X + (size_t)(bm0 + row) * 256 + ku);
            Xb[row * 17 + ku] = v.x; Xb[row * 17 + ku + 1] = v.y;
            Xb[row * 17 + ku + 2] = v.z; Xb[row * 17 + ku + 3] = v.w;
        }
        float* Wb = Wt;
        #pragma unroll
        for (int u = 0; u < 4; ++u) {
            int i = tid + u * 256;
            int kk = i >> 6, c4 = i & 63;
            float4 v = *(const float4*)(W1 + (size_t)kk * 256 + 4 * c4);
            *(float4*)(Wb + kk * 256 + 4 * c4) = v;
        }
    }
    __syncthreads();

    #pragma unroll 1
    for (int kc = 0; kc < 16; ++kc) {
        const int b = kc & 1;
        if (kc < 15) {
            const int kn = kc + 1;
            float* Xb = Xs + (b ^ 1) * XS_BUF;
            #pragma unroll
            for (int u = 0; u < 2; ++u) {
                int t = tid + u * 256;
                int row = t >> 2, ku = (t & 3) * 4;
                float4 v = *(const float4*)(X + (size_t)(bm0 + row) * 256 + kn * 16 + ku);
                Xb[row * 17 + ku] = v.x; Xb[row * 17 + ku + 1] = v.y;
                Xb[row * 17 + ku + 2] = v.z; Xb[row * 17 + ku + 3] = v.w;
            }
            float* Wb = Wt + (b ^ 1) * WT_BUF;
            #pragma unroll
            for (int u = 0; u < 4; ++u) {
                int i = tid + u * 256;
                int kk = i >> 6, c4 = i & 63;
                float4 v = *(const float4*)(W1 + (size_t)(kn * 16 + kk) * 256 + 4 * c4);
                *(float4*)(Wb + kk * 256 + 4 * c4) = v;
            }
        }
        const float* Xb  = Xs + b * XS_BUF;
        const ULL* Wt64b = (const ULL*)Wt + b * (WT_BUF / 2);
        #pragma unroll 4
        for (int kk = 0; kk < 16; ++kk) {
            ULL Av[8], Bv[8];
            #pragma unroll
            for (int p = 0; p < 8; ++p) Av[p] = f2dup(Xb[(tr + 16 * p) * 17 + kk]);
            #pragma unroll
            for (int j = 0; j < 8; ++j) Bv[j] = Wt64b[kk * 128 + tc + 16 * j];
            #pragma unroll
            for (int p = 0; p < 8; ++p)
                #pragma unroll
                for (int j = 0; j < 8; ++j)
                    acc[p][j] = ffma2(Av[p], Bv[j], acc[p][j]);
        }
        __syncthreads();
    }

    // epilogue 1: bias + relu -> h
    #pragma unroll
    for (int j = 0; j < 8; ++j) {
        float2 bb = ((const float2*)b1)[tc + 16 * j];
        #pragma unroll
        for (int p = 0; p < 8; ++p) {
            float2 v = f2unpack(acc[p][j]);
            v.x = fmaxf(v.x + bb.x, 0.0f);
            v.y = fmaxf(v.y + bb.y, 0.0f);
            int r = tr + 16 * p;
            h[r * H_STRIDE + 2 * (tc + 16 * j)]     = v.x;
            h[r * H_STRIDE + 2 * (tc + 16 * j) + 1] = v.y;
        }
    }
    // stage W2 kc=0 -> buffer 0 (Wt buf0 dead since layer-1 kc=14)
    {
        float* Wb = Wt;
        #pragma unroll
        for (int u = 0; u < 4; ++u) {
            int i = tid + u * 256;
            int kk = i >> 6, c4 = i & 63;
            float4 v = *(const float4*)(W2 + (size_t)kk * 256 + 4 * c4);
            *(float4*)(Wb + kk * 256 + 4 * c4) = v;
        }
    }
    __syncthreads();

    // ---------------- Layer 2: h = relu(h @ W2 + b2) ----------------
    #pragma unroll
    for (int p = 0; p < 8; ++p)
        #pragma unroll
        for (int j = 0; j < 8; ++j) acc[p][j] = 0ULL;

    #pragma unroll 1
    for (int kc = 0; kc < 16; ++kc) {
        const int b = kc & 1;
        if (kc < 15) {
            const int kn = kc + 1;
            float* Wb = Wt + (b ^ 1) * WT_BUF;
            #pragma unroll
            for (int u = 0; u < 4; ++u) {
                int i = tid + u * 256;
                int kk = i >> 6, c4 = i & 63;
                float4 v = *(const float4*)(W2 + (size_t)(kn * 16 + kk) * 256 + 4 * c4);
                *(float4*)(Wb + kk * 256 + 4 * c4) = v;
            }
        }
        const ULL* Wt64b = (const ULL*)Wt + b * (WT_BUF / 2);
        const int k0 = kc * 16;
        #pragma unroll 4
        for (int kk = 0; kk < 16; ++kk) {
            ULL Av[8], Bv[8];
            #pragma unroll
            for (int p = 0; p < 8; ++p) Av[p] = f2dup(h[(tr + 16 * p) * H_STRIDE + k0 + kk]);
            #pragma unroll
            for (int j = 0; j < 8; ++j) Bv[j] = Wt64b[kk * 128 + tc + 16 * j];
            #pragma unroll
            for (int p = 0; p < 8; ++p)
                #pragma unroll
                for (int j = 0; j < 8; ++j)
                    acc[p][j] = ffma2(Av[p], Bv[j], acc[p][j]);
        }
        __syncthreads();
    }

    // epilogue 2: bias + relu -> h (all layer-2 reads completed at final sync)
    #pragma unroll
    for (int j = 0; j < 8; ++j) {
        float2 bb = ((const float2*)b2)[tc + 16 * j];
        #pragma unroll
        for (int p = 0; p < 8; ++p) {
            float2 v = f2unpack(acc[p][j]);
            v.x = fmaxf(v.x + bb.x, 0.0f);
            v.y = fmaxf(v.y + bb.y, 0.0f);
            int r = tr + 16 * p;
            h[r * H_STRIDE + 2 * (tc + 16 * j)]     = v.x;
            h[r * H_STRIDE + 2 * (tc + 16 * j) + 1] = v.y;
        }
    }
    __syncthreads();

    // ---------------- Layer 3: logits = h @ W3 + b3 ----------------
    {
        const int rp = tid & 63;          // rows rp and rp+64
        const int g  = tid >> 6;          // cols 6g..6g+5 (3 colpairs)
        const float* hr0 = h + rp * H_STRIDE;
        const float* hr1 = h + (rp + 64) * H_STRIDE;
        const ULL* W3s64 = (const ULL*)W3s;
        ULL a3[2][3];
        #pragma unroll
        for (int j = 0; j < 3; ++j) { a3[0][j] = 0ULL; a3[1][j] = 0ULL; }
        #pragma unroll 8
        for (int k = 0; k < 256; ++k) {
            ULL a0 = f2dup(hr0[k]);
            ULL a1 = f2dup(hr1[k]);
            #pragma unroll
            for (int j = 0; j < 3; ++j) {
                ULL w = W3s64[k * 12 + 3 * g + j];
                a3[0][j] = ffma2(a0, w, a3[0][j]);
                a3[1][j] = ffma2(a1, w, a3[1][j]);
            }
        }
        #pragma unroll
        for (int j = 0; j < 3; ++j) {
            float2 bb = ((const float2*)b3)[3 * g + j];
            float2 v0 = f2unpack(a3[0][j]);
            float2 v1 = f2unpack(a3[1][j]);
            logit_s[rp * 25 + 6 * g + 2 * j]            = v0.x + bb.x;
            logit_s[rp * 25 + 6 * g + 2 * j + 1]        = v0.y + bb.y;
            logit_s[(rp + 64) * 25 + 6 * g + 2 * j]     = v1.x + bb.x;
            logit_s[(rp + 64) * 25 + 6 * g + 2 * j + 1] = v1.y + bb.y;
        }
    }
    __syncthreads();

    // ---------------- Top-6 of 22 selected + write ----------------
    if (tid < 128) {
        const int row = bm0 + tid;
        float v[24];
        #pragma unroll
        for (int c = 0; c < 24; ++c) v[c] = logit_s[tid * 25 + c];

        unsigned chosen = 1u | (1u << 12);
        #pragma unroll
        for (int it = 0; it < 6; ++it) {
            float best = -3.402823466e38f;
            int bi = 1;
            #pragma unroll
            for (int c = 1; c < 24; ++c) {
                if (c == 12) continue;
                bool free_ = !((chosen >> c) & 1u);
                if (free_ && v[c] > best) { best = v[c]; bi = c; }  // strict >: lower index wins ties
            }
            chosen |= (1u << bi);
        }

        float o[24];
        #pragma unroll
        for (int c = 0; c < 24; ++c) o[c] = ((chosen >> c) & 1u) ? 1.0f : 0.0f;
        float4* op = (float4*)(out + (size_t)row * 24);
        #pragma unroll
        for (int g2 = 0; g2 < 6; ++g2)
            op[g2] = make_float4(o[4 * g2], o[4 * g2 + 1], o[4 * g2 + 2], o[4 * g2 + 3]);
    }
}

extern "C" void kernel_launch(void* const* d_in, const int* in_sizes, int n_in,
                              void* d_out, int out_size) {
    const float* X  = (const float*)d_in[0];
    const float* W1 = (const float*)d_in[1];
    const float* b1 = (const float*)d_in[2];
    const float* W2 = (const float*)d_in[3];
    const float* b2 = (const float*)d_in[4];
    const float* W3 = (const float*)d_in[5];
    const float* b3 = (const float*)d_in[6];
    float* out = (float*)d_out;

    int B = in_sizes[0] / 256;
    cudaFuncSetAttribute(fused_mlp_topk, cudaFuncAttributeMaxDynamicSharedMemorySize, SMEM_BYTES);
    fused_mlp_topk<<<B / 128, 256, SMEM_BYTES>>>(X, W1, b1, W2, b2, W3, b3, out);
}